// round 13
// baseline (speedup 1.0000x reference)
#include <cuda_runtime.h>

#define Bn   1024
#define Kseg 160
#define WS   12
#define G    36
#define DH   1024
#define TPAD 168            // Kseg + 8 prefetch pad
#define STR4 (Bn * WS)      // float4 stride between t slots

typedef unsigned long long u64;

// Scratch (static device globals — no allocation)
__device__ float4 g_gi[TPAD * Bn * WS];    // [t][b][j] = {0.5*r, 0.5*z, n_raw, 0}
__device__ float4 g_pegi4[Kseg * WS];      // [k][j] = {0.5*pr, 0.5*pz, pn_raw, 0}
__device__ float4 g_wdec[Kseg * WS * 4];   // [k][j][4]: w0..3,w4..7,w8..11,{beff,..}

// Warp-uniform weights -> constant path
__constant__ float cWih[G * WS];
__constant__ float cbih[G];
__constant__ float cbhh[G];

__device__ __forceinline__ float ftanh(float x) {
    float y; asm("tanh.approx.f32 %0, %1;" : "=f"(y) : "f"(x)); return y;
}
__device__ __forceinline__ u64 pk(float lo, float hi) {
    u64 r; asm("mov.b64 %0, {%1, %2};" : "=l"(r) : "f"(lo), "f"(hi)); return r;
}
__device__ __forceinline__ void upk(u64 v, float& lo, float& hi) {
    asm("mov.b64 {%0, %1}, %2;" : "=f"(lo), "=f"(hi) : "l"(v));
}
__device__ __forceinline__ u64 ffma2(u64 a, u64 b, u64 c) {
    u64 d; asm("fma.rn.f32x2 %0, %1, %2, %3;" : "=l"(d) : "l"(a), "l"(b), "l"(c));
    return d;
}

// ---------------------------------------------------------------------------
// Prep kernel: blocks 0..639 = encoder + gi, 640..799 = weff fold, 800 = pegi.
// ---------------------------------------------------------------------------
__global__ void __launch_bounds__(256) prep_kernel(
        const float* __restrict__ x,
        const float* __restrict__ enc_W,
        const float* __restrict__ enc_b,
        const float* __restrict__ dec_W1,
        const float* __restrict__ dec_b1,
        const float* __restrict__ dec_W2,
        const float* __restrict__ dec_b2) {
    __shared__ float sraw[DH * WS];   // 48 KB, reused by branches

    if (blockIdx.x < 640) {
        // ------------------- encoder + gi -------------------
        float* sEW = sraw;            // 144
        float* sEB = sraw + 144;      // 12
        float* sg  = sraw + 192;      // 256*37 = 9472
        int k = blockIdx.x >> 2;
        int bbase = (blockIdx.x & 3) << 8;
        int b = bbase + threadIdx.x;

        {
            int t = threadIdx.x;
            if (t < WS * WS) sEW[t] = enc_W[k * (WS * WS) + t];
            if (t < WS) sEB[t] = enc_b[k * WS + t];
        }
        __syncthreads();

        const float4* xr4 = (const float4*)(x + (size_t)b * 1920 + k * WS);
        float4 x0 = xr4[0], x1 = xr4[1], x2 = xr4[2];
        float xv[WS] = {x0.x, x0.y, x0.z, x0.w, x1.x, x1.y, x1.z, x1.w,
                        x2.x, x2.y, x2.z, x2.w};

        float xs[WS];
#pragma unroll
        for (int o = 0; o < WS; ++o) {
            float a = sEB[o];
#pragma unroll
            for (int i = 0; i < WS; ++i) a = fmaf(xv[i], sEW[i * WS + o], a);
            xs[o] = fmaxf(a, 0.0f);
        }

        float* sgr = sg + threadIdx.x * 37;
#pragma unroll
        for (int g = 0; g < G; ++g) {
            float a = cbih[g] + ((g < 24) ? cbhh[g] : 0.0f);   // fold bhh_r,z
#pragma unroll
            for (int o = 0; o < WS; ++o) a = fmaf(xs[o], cWih[g * WS + o], a);
            sgr[g] = a;
        }
        __syncthreads();

        float4* dst = g_gi + ((size_t)k * Bn + bbase) * WS;
        for (int i = threadIdx.x; i < 256 * WS; i += 256) {
            int bl = i / WS;
            int j = i - bl * WS;
            const float* s = sg + bl * 37;
            dst[i] = make_float4(0.5f * s[j], 0.5f * s[12 + j], s[24 + j], 0.0f);
        }
        return;
    }

    if (blockIdx.x == 800) {
        // ------------------- pegi table -------------------
        int k = threadIdx.x;
        if (k >= Kseg) return;
        float pe[WS];
        const float c = -9.210340371976184f / 12.0f;   // -ln(10000)/d
#pragma unroll
        for (int j = 0; j < 6; ++j) {
            float div = expf(c * (float)(2 * j));
            float ang = (float)k * div;
            pe[2 * j]     = sinf(ang);
            pe[2 * j + 1] = cosf(ang);
        }
        float ch = sinf((float)k);
#pragma unroll
        for (int o = 0; o < WS; ++o) pe[o] += ch;
        float pg[G];
#pragma unroll
        for (int g = 0; g < G; ++g) {
            float a = 0.0f;
#pragma unroll
            for (int o = 0; o < WS; ++o) a = fmaf(pe[o], cWih[g * WS + o], a);
            pg[g] = a;
        }
#pragma unroll
        for (int j = 0; j < WS; ++j)
            g_pegi4[k * WS + j] = make_float4(0.5f * pg[j], 0.5f * pg[12 + j],
                                              pg[24 + j], 0.0f);
        return;
    }

    // ------------------- weff fold (k = blockIdx-640) -------------------
    {
        float* w2s = sraw;
        int k = blockIdx.x - 640;
        const float4* W24 = (const float4*)(dec_W2 + (size_t)k * DH * WS);
        float4* w2s4 = (float4*)w2s;
        for (int i = threadIdx.x; i < DH * WS / 4; i += 256) w2s4[i] = W24[i];
        __syncthreads();

        float* wdecF = (float*)g_wdec;        // [k][j][16] floats
        int t = threadIdx.x;
        if (t < 144) {
            int d = t / WS, o = t - (t / WS) * WS;
            const float4* w14 = (const float4*)(dec_W1 + ((size_t)k * WS + d) * DH);
            float a0 = 0.f, a1 = 0.f, a2 = 0.f, a3 = 0.f;
            float a4 = 0.f, a5 = 0.f, a6 = 0.f, a7 = 0.f;
            for (int q = 0; q < DH / 4; q += 2) {
                float4 u = w14[q], v = w14[q + 1];
                int h = q * 4;
                a0 = fmaf(u.x, w2s[(h + 0) * WS + o], a0);
                a1 = fmaf(u.y, w2s[(h + 1) * WS + o], a1);
                a2 = fmaf(u.z, w2s[(h + 2) * WS + o], a2);
                a3 = fmaf(u.w, w2s[(h + 3) * WS + o], a3);
                a4 = fmaf(v.x, w2s[(h + 4) * WS + o], a4);
                a5 = fmaf(v.y, w2s[(h + 5) * WS + o], a5);
                a6 = fmaf(v.z, w2s[(h + 6) * WS + o], a6);
                a7 = fmaf(v.w, w2s[(h + 7) * WS + o], a7);
            }
            wdecF[((size_t)k * WS + o) * 16 + d] =
                ((a0 + a1) + (a2 + a3)) + ((a4 + a5) + (a6 + a7));
        } else if (t < 156) {
            int o = t - 144;
            const float4* b14 = (const float4*)(dec_b1 + (size_t)k * DH);
            float a0 = dec_b2[k * WS + o], a1 = 0.f, a2 = 0.f, a3 = 0.f;
            for (int q = 0; q < DH / 4; ++q) {
                float4 u = b14[q];
                int h = q * 4;
                a0 = fmaf(u.x, w2s[(h + 0) * WS + o], a0);
                a1 = fmaf(u.y, w2s[(h + 1) * WS + o], a1);
                a2 = fmaf(u.z, w2s[(h + 2) * WS + o], a2);
                a3 = fmaf(u.w, w2s[(h + 3) * WS + o], a3);
            }
            wdecF[((size_t)k * WS + o) * 16 + 12] = (a0 + a1) + (a2 + a3);
        }
    }
}

// ---------------------------------------------------------------------------
// RNN + fused decoder. R12 structure; phase 1 prefetch ring deepened to 8
// (DRAM latency / depth is the step-time floor); phase 2 stays at 4 (L2-hot).
// ---------------------------------------------------------------------------
__device__ __forceinline__ void bcast2(float h, u64* hp) {
#pragma unroll
    for (int m = 0; m < 6; ++m) {
        float h0 = __shfl_sync(0xffffffffu, h, 2 * m, 16);
        float h1 = __shfl_sync(0xffffffffu, h, 2 * m + 1, 16);
        hp[m] = pk(h0, h1);
    }
}

__device__ __forceinline__ float gates2(const u64* hp, float gr, float gz,
                                        float gn, float bnp,
                                        const u64* wR, const u64* wZ,
                                        const u64* wN, float h) {
    u64 aR = pk(gr, 0.f), aZ = pk(gz, 0.f), aN = pk(bnp, 0.f);
#pragma unroll
    for (int m = 0; m < 6; ++m) {
        aR = ffma2(wR[m], hp[m], aR);
        aZ = ffma2(wZ[m], hp[m], aZ);
        aN = ffma2(wN[m], hp[m], aN);
    }
    float rl, rh, zl, zh, nl, nh;
    upk(aR, rl, rh); upk(aZ, zl, zh); upk(aN, nl, nh);
    float r = fmaf(0.5f, ftanh(rl + rh), 0.5f);        // sigmoid
    float z = fmaf(0.5f, ftanh(zl + zh), 0.5f);
    float n = ftanh(fmaf(r, nl + nh, gn));             // direct tanh
    return fmaf(z, h - n, n);
}

__device__ __forceinline__ float decacc2(const u64* hp, const float4* wb) {
    const u64* w = (const u64*)wb;          // 6 packed pairs, then {beff,..}
    u64 acc = pk(wb[3].x, 0.f);
#pragma unroll
    for (int m = 0; m < 6; ++m) acc = ffma2(w[m], hp[m], acc);
    float lo, hi; upk(acc, lo, hi);
    return lo + hi;
}

extern __shared__ float4 s_dyn[];   // [0..1919]: pegis, [1920..9599]: wdec

__global__ void __launch_bounds__(128) rnn_kernel(const float* __restrict__ Whh,
                                                  const float* __restrict__ bhh,
                                                  float* __restrict__ out) {
    float4* pegis = s_dyn;                     // 30 KB
    float4* wsm   = s_dyn + Kseg * WS;         // 120 KB
    int lane16 = threadIdx.x & 15;
    int row = blockIdx.x * 8 + (threadIdx.x >> 4);   // 0..1023
    bool act = (lane16 < WS);
    int j = act ? lane16 : (WS - 1);

    u64 wR[6], wZ[6], wN[6];
#pragma unroll
    for (int m = 0; m < 6; ++m) {
        wR[m] = pk(0.5f * Whh[j * 12 + 2 * m],        0.5f * Whh[j * 12 + 2 * m + 1]);
        wZ[m] = pk(0.5f * Whh[(12 + j) * 12 + 2 * m], 0.5f * Whh[(12 + j) * 12 + 2 * m + 1]);
        wN[m] = pk(Whh[(24 + j) * 12 + 2 * m],        Whh[(24 + j) * 12 + 2 * m + 1]);
    }
    float bnp = bhh[24 + j];

    for (int i = threadIdx.x; i < Kseg * WS; i += 128) pegis[i] = g_pegi4[i];
    for (int i = threadIdx.x; i < Kseg * WS * 4; i += 128) wsm[i] = g_wdec[i];
    __syncthreads();

    const float4* pA = g_gi + (size_t)row * WS + j;
    float h = 0.0f;

    // ---------------- phase 1: first GRU, 8-deep prefetch ring --------------
    {
        float4 a0 = pA[0],        a1 = pA[STR4],     a2 = pA[2 * STR4];
        float4 a3 = pA[3 * STR4], a4 = pA[4 * STR4], a5 = pA[5 * STR4];
        float4 a6 = pA[6 * STR4], a7 = pA[7 * STR4];
        const float4* q = pA + 8 * STR4;
        for (int t = 0; t < Kseg; t += 8) {
            u64 hp[6];
            bcast2(h, hp); h = gates2(hp, a0.x, a0.y, a0.z, bnp, wR, wZ, wN, h);
            a0 = q[0];
            bcast2(h, hp); h = gates2(hp, a1.x, a1.y, a1.z, bnp, wR, wZ, wN, h);
            a1 = q[STR4];
            bcast2(h, hp); h = gates2(hp, a2.x, a2.y, a2.z, bnp, wR, wZ, wN, h);
            a2 = q[2 * STR4];
            bcast2(h, hp); h = gates2(hp, a3.x, a3.y, a3.z, bnp, wR, wZ, wN, h);
            a3 = q[3 * STR4];
            bcast2(h, hp); h = gates2(hp, a4.x, a4.y, a4.z, bnp, wR, wZ, wN, h);
            a4 = q[4 * STR4];
            bcast2(h, hp); h = gates2(hp, a5.x, a5.y, a5.z, bnp, wR, wZ, wN, h);
            a5 = q[5 * STR4];
            bcast2(h, hp); h = gates2(hp, a6.x, a6.y, a6.z, bnp, wR, wZ, wN, h);
            a6 = q[6 * STR4];
            bcast2(h, hp); h = gates2(hp, a7.x, a7.y, a7.z, bnp, wR, wZ, wN, h);
            a7 = q[7 * STR4];
            q += 8 * STR4;
        }
    }

    // ---------------- phase 2: second GRU + fused decoder (L2-hot) ----------
    float* outp = out + (size_t)row * 1920 + j;
    const float4* wj = wsm + (size_t)j * 4;    // + t*48 per step

    {
        float4 a0 = pA[0], a1 = pA[STR4], a2 = pA[2 * STR4], a3 = pA[3 * STR4];
        const float4* q = pA + 4 * STR4;
        const float4* pg = pegis + j;

#define STEP2(AREG, PV, TT, QOFF)                                           \
        {                                                                   \
            u64 hp[6];                                                      \
            bcast2(h, hp);                                                  \
            if (act && (TT) > 0) {                                          \
                float oa = decacc2(hp, wj + (size_t)((TT) - 1) * 48);       \
                outp[((TT) - 1) * 12] = oa;                                 \
            }                                                               \
            h = gates2(hp, AREG.x + PV.x, AREG.y + PV.y, AREG.z + PV.z,     \
                       bnp, wR, wZ, wN, h);                                 \
            AREG = q[QOFF];                                                 \
        }

        for (int t = 0; t < Kseg; t += 4) {
            float4 p0 = pg[0], p1 = pg[WS], p2 = pg[2 * WS], p3 = pg[3 * WS];
            pg += 4 * WS;
            STEP2(a0, p0, t + 0, 0);
            STEP2(a1, p1, t + 1, STR4);
            STEP2(a2, p2, t + 2, 2 * STR4);
            STEP2(a3, p3, t + 3, 3 * STR4);
            q += 4 * STR4;
        }
#undef STEP2

        // tail: out for t = Kseg-1
        u64 hp[6];
        bcast2(h, hp);
        if (act) {
            float oa = decacc2(hp, wj + (size_t)(Kseg - 1) * 48);
            outp[(Kseg - 1) * 12] = oa;
        }
    }
}

// ---------------------------------------------------------------------------
extern "C" void kernel_launch(void* const* d_in, const int* in_sizes, int n_in,
                              void* d_out, int out_size) {
    const float* x     = (const float*)d_in[0];
    const float* enc_W = (const float*)d_in[1];
    const float* enc_b = (const float*)d_in[2];
    const float* Wih   = (const float*)d_in[3];
    const float* Whh   = (const float*)d_in[4];
    const float* bih   = (const float*)d_in[5];
    const float* bhh   = (const float*)d_in[6];
    const float* dW1   = (const float*)d_in[7];
    const float* db1   = (const float*)d_in[8];
    const float* dW2   = (const float*)d_in[9];
    const float* db2   = (const float*)d_in[10];
    float* out = (float*)d_out;

    const int RNN_SMEM = Kseg * WS * 5 * 16;   // 153600 B
    cudaFuncSetAttribute(rnn_kernel,
                         cudaFuncAttributeMaxDynamicSharedMemorySize,
                         RNN_SMEM);

    cudaMemcpyToSymbolAsync(cWih, Wih, G * WS * sizeof(float), 0,
                            cudaMemcpyDeviceToDevice);
    cudaMemcpyToSymbolAsync(cbih, bih, G * sizeof(float), 0,
                            cudaMemcpyDeviceToDevice);
    cudaMemcpyToSymbolAsync(cbhh, bhh, G * sizeof(float), 0,
                            cudaMemcpyDeviceToDevice);

    prep_kernel<<<801, 256>>>(x, enc_W, enc_b, dW1, db1, dW2, db2);
    rnn_kernel<<<128, 128, RNN_SMEM>>>(Whh, bhh, out);
}

// round 14
// speedup vs baseline: 1.0881x; 1.0881x over previous
#include <cuda_runtime.h>

#define Bn   1024
#define Kseg 160
#define WS   12
#define G    36
#define DH   1024
#define TPAD 168            // Kseg + 8 prefetch pad
#define STR4 (Bn * WS)      // float4 stride between t slots

typedef unsigned long long u64;

// Scratch (static device globals — no allocation)
__device__ float4 g_gi[TPAD * Bn * WS];        // [t][b][j] = {0.5*r, 0.5*z, n_raw, 0}
__device__ float4 g_pegi4[Kseg * WS];          // [k][j] = {0.5*pr, 0.5*pz, pn_raw, 0}
__device__ float4 g_wdec[(Kseg + 2) * WS * 4]; // [k][j][4] (+2 pad k-slots for prefetch)

// Warp-uniform weights -> constant path
__constant__ float cWih[G * WS];
__constant__ float cbih[G];
__constant__ float cbhh[G];

__device__ __forceinline__ float ftanh(float x) {
    float y; asm("tanh.approx.f32 %0, %1;" : "=f"(y) : "f"(x)); return y;
}
__device__ __forceinline__ u64 pk(float lo, float hi) {
    u64 r; asm("mov.b64 %0, {%1, %2};" : "=l"(r) : "f"(lo), "f"(hi)); return r;
}
__device__ __forceinline__ void upk(u64 v, float& lo, float& hi) {
    asm("mov.b64 {%0, %1}, %2;" : "=f"(lo), "=f"(hi) : "l"(v));
}
__device__ __forceinline__ u64 ffma2(u64 a, u64 b, u64 c) {
    u64 d; asm("fma.rn.f32x2 %0, %1, %2, %3;" : "=l"(d) : "l"(a), "l"(b), "l"(c));
    return d;
}
__device__ __forceinline__ float4 ldgcs(const float4* p) {   // streaming load
    float4 v;
    asm("ld.global.cs.v4.f32 {%0,%1,%2,%3}, [%4];"
        : "=f"(v.x), "=f"(v.y), "=f"(v.z), "=f"(v.w) : "l"(p));
    return v;
}

// ---------------------------------------------------------------------------
// Prep kernel: blocks 0..639 = encoder + gi, 640..799 = weff fold, 800 = pegi.
// (unchanged from R13)
// ---------------------------------------------------------------------------
__global__ void __launch_bounds__(256) prep_kernel(
        const float* __restrict__ x,
        const float* __restrict__ enc_W,
        const float* __restrict__ enc_b,
        const float* __restrict__ dec_W1,
        const float* __restrict__ dec_b1,
        const float* __restrict__ dec_W2,
        const float* __restrict__ dec_b2) {
    __shared__ float sraw[DH * WS];   // 48 KB, reused by branches

    if (blockIdx.x < 640) {
        float* sEW = sraw;            // 144
        float* sEB = sraw + 144;      // 12
        float* sg  = sraw + 192;      // 256*37 = 9472
        int k = blockIdx.x >> 2;
        int bbase = (blockIdx.x & 3) << 8;
        int b = bbase + threadIdx.x;

        {
            int t = threadIdx.x;
            if (t < WS * WS) sEW[t] = enc_W[k * (WS * WS) + t];
            if (t < WS) sEB[t] = enc_b[k * WS + t];
        }
        __syncthreads();

        const float4* xr4 = (const float4*)(x + (size_t)b * 1920 + k * WS);
        float4 x0 = xr4[0], x1 = xr4[1], x2 = xr4[2];
        float xv[WS] = {x0.x, x0.y, x0.z, x0.w, x1.x, x1.y, x1.z, x1.w,
                        x2.x, x2.y, x2.z, x2.w};

        float xs[WS];
#pragma unroll
        for (int o = 0; o < WS; ++o) {
            float a = sEB[o];
#pragma unroll
            for (int i = 0; i < WS; ++i) a = fmaf(xv[i], sEW[i * WS + o], a);
            xs[o] = fmaxf(a, 0.0f);
        }

        float* sgr = sg + threadIdx.x * 37;
#pragma unroll
        for (int g = 0; g < G; ++g) {
            float a = cbih[g] + ((g < 24) ? cbhh[g] : 0.0f);   // fold bhh_r,z
#pragma unroll
            for (int o = 0; o < WS; ++o) a = fmaf(xs[o], cWih[g * WS + o], a);
            sgr[g] = a;
        }
        __syncthreads();

        float4* dst = g_gi + ((size_t)k * Bn + bbase) * WS;
        for (int i = threadIdx.x; i < 256 * WS; i += 256) {
            int bl = i / WS;
            int j = i - bl * WS;
            const float* s = sg + bl * 37;
            dst[i] = make_float4(0.5f * s[j], 0.5f * s[12 + j], s[24 + j], 0.0f);
        }
        return;
    }

    if (blockIdx.x == 800) {
        int k = threadIdx.x;
        if (k >= Kseg) return;
        float pe[WS];
        const float c = -9.210340371976184f / 12.0f;   // -ln(10000)/d
#pragma unroll
        for (int j = 0; j < 6; ++j) {
            float div = expf(c * (float)(2 * j));
            float ang = (float)k * div;
            pe[2 * j]     = sinf(ang);
            pe[2 * j + 1] = cosf(ang);
        }
        float ch = sinf((float)k);
#pragma unroll
        for (int o = 0; o < WS; ++o) pe[o] += ch;
        float pg[G];
#pragma unroll
        for (int g = 0; g < G; ++g) {
            float a = 0.0f;
#pragma unroll
            for (int o = 0; o < WS; ++o) a = fmaf(pe[o], cWih[g * WS + o], a);
            pg[g] = a;
        }
#pragma unroll
        for (int j = 0; j < WS; ++j)
            g_pegi4[k * WS + j] = make_float4(0.5f * pg[j], 0.5f * pg[12 + j],
                                              pg[24 + j], 0.0f);
        return;
    }

    {
        float* w2s = sraw;
        int k = blockIdx.x - 640;
        const float4* W24 = (const float4*)(dec_W2 + (size_t)k * DH * WS);
        float4* w2s4 = (float4*)w2s;
        for (int i = threadIdx.x; i < DH * WS / 4; i += 256) w2s4[i] = W24[i];
        __syncthreads();

        float* wdecF = (float*)g_wdec;        // [k][j][16] floats
        int t = threadIdx.x;
        if (t < 144) {
            int d = t / WS, o = t - (t / WS) * WS;
            const float4* w14 = (const float4*)(dec_W1 + ((size_t)k * WS + d) * DH);
            float a0 = 0.f, a1 = 0.f, a2 = 0.f, a3 = 0.f;
            float a4 = 0.f, a5 = 0.f, a6 = 0.f, a7 = 0.f;
            for (int q = 0; q < DH / 4; q += 2) {
                float4 u = w14[q], v = w14[q + 1];
                int h = q * 4;
                a0 = fmaf(u.x, w2s[(h + 0) * WS + o], a0);
                a1 = fmaf(u.y, w2s[(h + 1) * WS + o], a1);
                a2 = fmaf(u.z, w2s[(h + 2) * WS + o], a2);
                a3 = fmaf(u.w, w2s[(h + 3) * WS + o], a3);
                a4 = fmaf(v.x, w2s[(h + 4) * WS + o], a4);
                a5 = fmaf(v.y, w2s[(h + 5) * WS + o], a5);
                a6 = fmaf(v.z, w2s[(h + 6) * WS + o], a6);
                a7 = fmaf(v.w, w2s[(h + 7) * WS + o], a7);
            }
            wdecF[((size_t)k * WS + o) * 16 + d] =
                ((a0 + a1) + (a2 + a3)) + ((a4 + a5) + (a6 + a7));
        } else if (t < 156) {
            int o = t - 144;
            const float4* b14 = (const float4*)(dec_b1 + (size_t)k * DH);
            float a0 = dec_b2[k * WS + o], a1 = 0.f, a2 = 0.f, a3 = 0.f;
            for (int q = 0; q < DH / 4; ++q) {
                float4 u = b14[q];
                int h = q * 4;
                a0 = fmaf(u.x, w2s[(h + 0) * WS + o], a0);
                a1 = fmaf(u.y, w2s[(h + 1) * WS + o], a1);
                a2 = fmaf(u.z, w2s[(h + 2) * WS + o], a2);
                a3 = fmaf(u.w, w2s[(h + 3) * WS + o], a3);
            }
            wdecF[((size_t)k * WS + o) * 16 + 12] = (a0 + a1) + (a2 + a3);
        }
    }
}

// ---------------------------------------------------------------------------
// RNN + fused decoder. Same math as R13; launch config rebalanced to cut
// per-SM MIO contention: 64-thread blocks (2 warps), grid 256 -> 2-4 warps/SM
// instead of 8. wdec moved from smem to L1-resident global with 2-step
// register double-buffer (longlong2 loads feed FFMA2 directly).
// ---------------------------------------------------------------------------
__device__ __forceinline__ void bcast2(float h, u64* hp) {
#pragma unroll
    for (int m = 0; m < 6; ++m) {
        float h0 = __shfl_sync(0xffffffffu, h, 2 * m, 16);
        float h1 = __shfl_sync(0xffffffffu, h, 2 * m + 1, 16);
        hp[m] = pk(h0, h1);
    }
}

__device__ __forceinline__ float gates2(const u64* hp, float gr, float gz,
                                        float gn, float bnp,
                                        const u64* wR, const u64* wZ,
                                        const u64* wN, float h) {
    u64 aR = pk(gr, 0.f), aZ = pk(gz, 0.f), aN = pk(bnp, 0.f);
#pragma unroll
    for (int m = 0; m < 6; ++m) {
        aR = ffma2(wR[m], hp[m], aR);
        aZ = ffma2(wZ[m], hp[m], aZ);
        aN = ffma2(wN[m], hp[m], aN);
    }
    float rl, rh, zl, zh, nl, nh;
    upk(aR, rl, rh); upk(aZ, zl, zh); upk(aN, nl, nh);
    float r = fmaf(0.5f, ftanh(rl + rh), 0.5f);        // sigmoid
    float z = fmaf(0.5f, ftanh(zl + zh), 0.5f);
    float n = ftanh(fmaf(r, nl + nh, gn));             // direct tanh
    return fmaf(z, h - n, n);
}

__device__ __forceinline__ float decacc2u(const u64* hp, const u64* W, float be) {
    u64 acc = pk(be, 0.f);
#pragma unroll
    for (int m = 0; m < 6; ++m) acc = ffma2(W[m], hp[m], acc);
    float lo, hi; upk(acc, lo, hi);
    return lo + hi;
}

__global__ void __launch_bounds__(64) rnn_kernel(const float* __restrict__ Whh,
                                                 const float* __restrict__ bhh,
                                                 float* __restrict__ out) {
    __shared__ float4 pegis[Kseg * WS];        // 30 KB static
    int lane16 = threadIdx.x & 15;
    int row = blockIdx.x * 4 + (threadIdx.x >> 4);   // 0..1023
    bool act = (lane16 < WS);
    int j = act ? lane16 : (WS - 1);

    u64 wR[6], wZ[6], wN[6];
#pragma unroll
    for (int m = 0; m < 6; ++m) {
        wR[m] = pk(0.5f * Whh[j * 12 + 2 * m],        0.5f * Whh[j * 12 + 2 * m + 1]);
        wZ[m] = pk(0.5f * Whh[(12 + j) * 12 + 2 * m], 0.5f * Whh[(12 + j) * 12 + 2 * m + 1]);
        wN[m] = pk(Whh[(24 + j) * 12 + 2 * m],        Whh[(24 + j) * 12 + 2 * m + 1]);
    }
    float bnp = bhh[24 + j];

    for (int i = threadIdx.x; i < Kseg * WS; i += 64) pegis[i] = g_pegi4[i];
    __syncthreads();

    const float4* pA = g_gi + (size_t)row * WS + j;
    float h = 0.0f;

    // ---------------- phase 1: first GRU, 8-deep prefetch ring --------------
    {
        float4 a0 = ldgcs(pA),            a1 = ldgcs(pA + STR4);
        float4 a2 = ldgcs(pA + 2 * STR4), a3 = ldgcs(pA + 3 * STR4);
        float4 a4 = ldgcs(pA + 4 * STR4), a5 = ldgcs(pA + 5 * STR4);
        float4 a6 = ldgcs(pA + 6 * STR4), a7 = ldgcs(pA + 7 * STR4);
        const float4* q = pA + 8 * STR4;
        for (int t = 0; t < Kseg; t += 8) {
            u64 hp[6];
            bcast2(h, hp); h = gates2(hp, a0.x, a0.y, a0.z, bnp, wR, wZ, wN, h);
            a0 = ldgcs(q);
            bcast2(h, hp); h = gates2(hp, a1.x, a1.y, a1.z, bnp, wR, wZ, wN, h);
            a1 = ldgcs(q + STR4);
            bcast2(h, hp); h = gates2(hp, a2.x, a2.y, a2.z, bnp, wR, wZ, wN, h);
            a2 = ldgcs(q + 2 * STR4);
            bcast2(h, hp); h = gates2(hp, a3.x, a3.y, a3.z, bnp, wR, wZ, wN, h);
            a3 = ldgcs(q + 3 * STR4);
            bcast2(h, hp); h = gates2(hp, a4.x, a4.y, a4.z, bnp, wR, wZ, wN, h);
            a4 = ldgcs(q + 4 * STR4);
            bcast2(h, hp); h = gates2(hp, a5.x, a5.y, a5.z, bnp, wR, wZ, wN, h);
            a5 = ldgcs(q + 5 * STR4);
            bcast2(h, hp); h = gates2(hp, a6.x, a6.y, a6.z, bnp, wR, wZ, wN, h);
            a6 = ldgcs(q + 6 * STR4);
            bcast2(h, hp); h = gates2(hp, a7.x, a7.y, a7.z, bnp, wR, wZ, wN, h);
            a7 = ldgcs(q + 7 * STR4);
            q += 8 * STR4;
        }
    }

    // ---------------- phase 2: second GRU + fused decoder -------------------
    float* outp = out + (size_t)row * 1920 + j;
    const float4* wgj = g_wdec + (size_t)j * 4;       // + k*48 per step

    // wdec double buffers: E holds even-k entries, O holds odd-k entries.
#define LOADW(W, BIAS, KK)                                                  \
    {                                                                       \
        const longlong2* _p = (const longlong2*)(wgj + (size_t)(KK) * 48);  \
        longlong2 l0 = _p[0], l1 = _p[1], l2 = _p[2];                       \
        W[0] = (u64)l0.x; W[1] = (u64)l0.y;                                 \
        W[2] = (u64)l1.x; W[3] = (u64)l1.y;                                 \
        W[4] = (u64)l2.x; W[5] = (u64)l2.y;                                 \
        BIAS = wgj[(size_t)(KK) * 48 + 3].x;                                \
    }

    u64 WE[6], WO[6];
    float beE, beO;
    LOADW(WE, beE, 0);       // consumed at t=1  (wdec[0])
    LOADW(WO, beO, 1);       // consumed at t=2  (wdec[1])

    {
        float4 a0 = ldgcs(pA),            a1 = ldgcs(pA + STR4);
        float4 a2 = ldgcs(pA + 2 * STR4), a3 = ldgcs(pA + 3 * STR4);
        const float4* q = pA + 4 * STR4;
        const float4* pg = pegis + j;

// step TT consumes wdec[TT-1] from buffer WB, then reloads WB <- wdec[TT+1]
#define STEP2(AREG, PV, TT, QOFF, WB, BB)                                   \
        {                                                                   \
            u64 hp[6];                                                      \
            bcast2(h, hp);                                                  \
            if (act && (TT) > 0) {                                          \
                float oa = decacc2u(hp, WB, BB);                            \
                outp[((TT) - 1) * 12] = oa;                                 \
            }                                                               \
            h = gates2(hp, AREG.x + PV.x, AREG.y + PV.y, AREG.z + PV.z,     \
                       bnp, wR, wZ, wN, h);                                 \
            AREG = ldgcs(q + (QOFF));                                       \
            LOADW(WB, BB, (TT) + 1);                                        \
        }

        for (int t = 0; t < Kseg; t += 4) {
            float4 p0 = pg[0], p1 = pg[WS], p2 = pg[2 * WS], p3 = pg[3 * WS];
            pg += 4 * WS;
            STEP2(a0, p0, t + 0, 0,        WO, beO);   // consumes wdec[t-1] (odd)
            STEP2(a1, p1, t + 1, STR4,     WE, beE);   // consumes wdec[t]   (even)
            STEP2(a2, p2, t + 2, 2 * STR4, WO, beO);
            STEP2(a3, p3, t + 3, 3 * STR4, WE, beE);
            q += 4 * STR4;
        }
#undef STEP2

        // tail: out for t = Kseg-1 from WO (loaded at step 158)
        u64 hp[6];
        bcast2(h, hp);
        if (act) {
            float oa = decacc2u(hp, WO, beO);
            outp[(Kseg - 1) * 12] = oa;
        }
    }
#undef LOADW
}

// ---------------------------------------------------------------------------
extern "C" void kernel_launch(void* const* d_in, const int* in_sizes, int n_in,
                              void* d_out, int out_size) {
    const float* x     = (const float*)d_in[0];
    const float* enc_W = (const float*)d_in[1];
    const float* enc_b = (const float*)d_in[2];
    const float* Wih   = (const float*)d_in[3];
    const float* Whh   = (const float*)d_in[4];
    const float* bih   = (const float*)d_in[5];
    const float* bhh   = (const float*)d_in[6];
    const float* dW1   = (const float*)d_in[7];
    const float* db1   = (const float*)d_in[8];
    const float* dW2   = (const float*)d_in[9];
    const float* db2   = (const float*)d_in[10];
    float* out = (float*)d_out;

    cudaMemcpyToSymbolAsync(cWih, Wih, G * WS * sizeof(float), 0,
                            cudaMemcpyDeviceToDevice);
    cudaMemcpyToSymbolAsync(cbih, bih, G * sizeof(float), 0,
                            cudaMemcpyDeviceToDevice);
    cudaMemcpyToSymbolAsync(cbhh, bhh, G * sizeof(float), 0,
                            cudaMemcpyDeviceToDevice);

    prep_kernel<<<801, 256>>>(x, enc_W, enc_b, dW1, db1, dW2, db2);
    rnn_kernel<<<256, 64>>>(Whh, bhh, out);
}